// round 4
// baseline (speedup 1.0000x reference)
#include <cuda_runtime.h>
#include <cstdint>

// =====================================================================
// QuantLinear W8A8 — pure dp4a SIMT GEMM (sm_103a has no legacy tensor
// mma; mma.sync is emulated, so we go straight to the primitive).
//   acc[m,n] = sum_k Xq[m,k]*Wq[n,k]  (u8 x s8 -> s32, exact, dp4a)
//   Y = (acc - zp[m]*rowsumW[n]) * sa[m]*sw[n] + bias[n]
// GEMM: CTA 128x128, 256 threads, 8x8 strided register tiles,
// k-word-major smem (conflict-free LDS.32), 3-stage cp.async.
// =====================================================================

static constexpr int M_MAX = 8192;
static constexpr int N_MAX = 4096;
static constexpr int K_MAX = 4096;

__device__ uint8_t g_xq[(size_t)M_MAX * K_MAX];
__device__ int8_t  g_wq[(size_t)N_MAX * K_MAX];
__device__ float   g_ascale[M_MAX];
__device__ float   g_azp[M_MAX];
__device__ float   g_wscale[N_MAX];
__device__ float   g_wrowsum[N_MAX];

// ======================= PTX helpers =======================

__device__ __forceinline__ uint32_t smem_to_u32(const void* p) {
    uint32_t a;
    asm("{ .reg .u64 t; cvta.to.shared.u64 t, %1; cvt.u32.u64 %0, t; }"
        : "=r"(a) : "l"(p));
    return a;
}

__device__ __forceinline__ void cp_async4(uint32_t smem_addr, const void* gptr) {
    asm volatile("cp.async.ca.shared.global [%0], [%1], 4;\n"
                 :: "r"(smem_addr), "l"(gptr) : "memory");
}

#define CP_ASYNC_COMMIT() asm volatile("cp.async.commit_group;\n" ::: "memory")
#define CP_ASYNC_WAIT(n)  asm volatile("cp.async.wait_group %0;\n" :: "n"(n) : "memory")

// d += dot(u8x4(a), s8x4(b))  -- exact integer
__device__ __forceinline__ int dp4a_us(uint32_t a, uint32_t b, int c) {
    int d;
    asm("dp4a.u32.s32 %0, %1, %2, %3;" : "=r"(d) : "r"(a), "r"(b), "r"(c));
    return d;
}

// ======================= quantization kernels =======================

__global__ void __launch_bounds__(256) quant_w_kernel(const float* __restrict__ w, int K) {
    const int n = blockIdx.x;
    const float4* row = reinterpret_cast<const float4*>(w + (size_t)n * K);
    const int nv = K >> 2;

    float amax = 0.0f;
    for (int i = threadIdx.x; i < nv; i += blockDim.x) {
        float4 v = row[i];
        amax = fmaxf(amax, fmaxf(fmaxf(fabsf(v.x), fabsf(v.y)),
                                 fmaxf(fabsf(v.z), fabsf(v.w))));
    }
    #pragma unroll
    for (int o = 16; o; o >>= 1)
        amax = fmaxf(amax, __shfl_xor_sync(0xFFFFFFFF, amax, o));

    __shared__ float s_amax[8];
    __shared__ float s_inv;
    const int wid = threadIdx.x >> 5;
    if ((threadIdx.x & 31) == 0) s_amax[wid] = amax;
    __syncthreads();
    if (threadIdx.x == 0) {
        float a = s_amax[0];
        #pragma unroll
        for (int i = 1; i < 8; i++) a = fmaxf(a, s_amax[i]);
        float sc = (a > 0.0f) ? __fdiv_rn(a, 127.0f) : 1.0f;
        g_wscale[n] = sc;
        s_inv = __fdiv_rn(1.0f, sc);
    }
    __syncthreads();
    const float inv = s_inv;

    int rsum = 0;
    uchar4* dst = reinterpret_cast<uchar4*>(g_wq + (size_t)n * K);
    for (int i = threadIdx.x; i < nv; i += blockDim.x) {
        float4 v = row[i];
        int q0 = (int)fminf(fmaxf(rintf(v.x * inv), -127.0f), 127.0f);
        int q1 = (int)fminf(fmaxf(rintf(v.y * inv), -127.0f), 127.0f);
        int q2 = (int)fminf(fmaxf(rintf(v.z * inv), -127.0f), 127.0f);
        int q3 = (int)fminf(fmaxf(rintf(v.w * inv), -127.0f), 127.0f);
        rsum += q0 + q1 + q2 + q3;
        uchar4 b;
        b.x = (uint8_t)(int8_t)q0; b.y = (uint8_t)(int8_t)q1;
        b.z = (uint8_t)(int8_t)q2; b.w = (uint8_t)(int8_t)q3;
        dst[i] = b;
    }
    #pragma unroll
    for (int o = 16; o; o >>= 1) rsum += __shfl_xor_sync(0xFFFFFFFF, rsum, o);
    __shared__ int s_sum[8];
    if ((threadIdx.x & 31) == 0) s_sum[wid] = rsum;
    __syncthreads();
    if (threadIdx.x == 0) {
        int t = s_sum[0];
        #pragma unroll
        for (int i = 1; i < 8; i++) t += s_sum[i];
        g_wrowsum[n] = (float)t;
    }
}

__global__ void __launch_bounds__(256) quant_x_kernel(const float* __restrict__ x, int K) {
    const int m = blockIdx.x;
    const float4* row = reinterpret_cast<const float4*>(x + (size_t)m * K);
    const int nv = K >> 2;

    float vmin = 3.0e38f, vmax = -3.0e38f;
    for (int i = threadIdx.x; i < nv; i += blockDim.x) {
        float4 v = row[i];
        vmin = fminf(vmin, fminf(fminf(v.x, v.y), fminf(v.z, v.w)));
        vmax = fmaxf(vmax, fmaxf(fmaxf(v.x, v.y), fmaxf(v.z, v.w)));
    }
    #pragma unroll
    for (int o = 16; o; o >>= 1) {
        vmin = fminf(vmin, __shfl_xor_sync(0xFFFFFFFF, vmin, o));
        vmax = fmaxf(vmax, __shfl_xor_sync(0xFFFFFFFF, vmax, o));
    }
    __shared__ float s_min[8], s_max[8];
    __shared__ float s_inv, s_zp;
    const int wid = threadIdx.x >> 5;
    if ((threadIdx.x & 31) == 0) { s_min[wid] = vmin; s_max[wid] = vmax; }
    __syncthreads();
    if (threadIdx.x == 0) {
        float mn = s_min[0], mx = s_max[0];
        #pragma unroll
        for (int i = 1; i < 8; i++) { mn = fminf(mn, s_min[i]); mx = fmaxf(mx, s_max[i]); }
        float rng = mx - mn;
        float sc = (rng > 0.0f) ? __fdiv_rn(rng, 255.0f) : 1.0f;
        float zp = rintf(__fdiv_rn(-mn, sc));
        g_ascale[m] = sc;
        g_azp[m] = zp;
        s_inv = __fdiv_rn(1.0f, sc);
        s_zp = zp;
    }
    __syncthreads();
    const float inv = s_inv, zp = s_zp;

    uchar4* dst = reinterpret_cast<uchar4*>(g_xq + (size_t)m * K);
    for (int i = threadIdx.x; i < nv; i += blockDim.x) {
        float4 v = row[i];
        float q0 = fminf(fmaxf(rintf(v.x * inv) + zp, 0.0f), 255.0f);
        float q1 = fminf(fmaxf(rintf(v.y * inv) + zp, 0.0f), 255.0f);
        float q2 = fminf(fmaxf(rintf(v.z * inv) + zp, 0.0f), 255.0f);
        float q3 = fminf(fmaxf(rintf(v.w * inv) + zp, 0.0f), 255.0f);
        uchar4 b;
        b.x = (uint8_t)q0; b.y = (uint8_t)q1; b.z = (uint8_t)q2; b.w = (uint8_t)q3;
        dst[i] = b;
    }
}

// ======================= dp4a GEMM kernel =======================
// CTA 128(M) x 128(N), K-chunk 32B (8 k-words). 256 threads = 16x16.
// Thread (ty,tx) owns rows {ty+16r} x cols {tx+16c}, r,c in 0..7.
// Smem k-word-major: As[stage][kw][m] so fragment loads are LDS.32
// broadcast (A) / 16-distinct-bank (B). 3-stage cp.async pipeline.

static constexpr int STAGES = 3;

__global__ void __launch_bounds__(256, 2)
gemm_kernel(float* __restrict__ out, const float* __restrict__ bias,
            int M, int N, int K) {
    __shared__ uint32_t As[STAGES][8][128];
    __shared__ uint32_t Bs[STAGES][8][128];
    const uint32_t sA0 = smem_to_u32(&As[0][0][0]);
    const uint32_t sB0 = smem_to_u32(&Bs[0][0][0]);

    const int tid = threadIdx.x;
    const int tx = tid & 15;
    const int ty = tid >> 4;
    const int m0 = blockIdx.y * 128;
    const int n0 = blockIdx.x * 128;

    const int KT = K >> 5;   // 32B K-chunks

    const uint8_t* gA = g_xq + (size_t)m0 * K;
    const uint8_t* gB = reinterpret_cast<const uint8_t*>(g_wq) + (size_t)n0 * K;

    // copy mapping: idx in [0,1024): m = idx>>3, w = idx&7
    // lanes cover consecutive k-words within a row -> coalesced 32B runs
    auto issue_stage = [&](int kt, int s) {
        if (kt < KT) {
            const uint32_t sa = sA0 + s * 4096;
            const uint32_t sb = sB0 + s * 4096;
            #pragma unroll
            for (int j = 0; j < 4; j++) {
                int idx = tid + j * 256;
                int m = idx >> 3;
                int w = idx & 7;
                uint32_t off = (uint32_t)(w * 512 + m * 4);
                const uint8_t* srcA = gA + (size_t)m * K + kt * 32 + w * 4;
                const uint8_t* srcB = gB + (size_t)m * K + kt * 32 + w * 4;
                cp_async4(sa + off, srcA);
                cp_async4(sb + off, srcB);
            }
        }
        CP_ASYNC_COMMIT();
    };

    int acc[8][8];
    #pragma unroll
    for (int r = 0; r < 8; r++)
        #pragma unroll
        for (int c = 0; c < 8; c++) acc[r][c] = 0;

    #pragma unroll
    for (int s = 0; s < STAGES - 1; s++) issue_stage(s, s);

    for (int kt = 0; kt < KT; kt++) {
        CP_ASYNC_WAIT(STAGES - 2);
        __syncthreads();

        issue_stage(kt + STAGES - 1, (kt + STAGES - 1) % STAGES);

        const int s = kt % STAGES;
        const uint32_t* __restrict__ Ak = &As[s][0][0];
        const uint32_t* __restrict__ Bk = &Bs[s][0][0];

        #pragma unroll
        for (int kk = 0; kk < 8; kk++) {
            uint32_t a[8], b[8];
            #pragma unroll
            for (int r = 0; r < 8; r++) a[r] = Ak[kk * 128 + ty + 16 * r];
            #pragma unroll
            for (int c = 0; c < 8; c++) b[c] = Bk[kk * 128 + tx + 16 * c];
            #pragma unroll
            for (int r = 0; r < 8; r++)
                #pragma unroll
                for (int c = 0; c < 8; c++)
                    acc[r][c] = dp4a_us(a[r], b[c], acc[r][c]);
        }
    }

    // ================= epilogue =================
    float sw[8], rs[8], bb[8];
    #pragma unroll
    for (int c = 0; c < 8; c++) {
        const int n = n0 + tx + 16 * c;
        sw[c] = g_wscale[n];
        rs[c] = g_wrowsum[n];
        bb[c] = bias[n];
    }
    #pragma unroll
    for (int r = 0; r < 8; r++) {
        const int m = m0 + ty + 16 * r;
        const float sa = g_ascale[m];
        const float zp = g_azp[m];
        float* orow = out + (size_t)m * N + n0 + tx;
        #pragma unroll
        for (int c = 0; c < 8; c++) {
            orow[16 * c] = ((float)acc[r][c] - zp * rs[c]) * (sa * sw[c]) + bb[c];
        }
    }
}

// ======================= launch =======================

extern "C" void kernel_launch(void* const* d_in, const int* in_sizes, int n_in,
                              void* d_out, int out_size) {
    const float* x    = (const float*)d_in[0];
    const float* w    = (const float*)d_in[1];
    const float* bias = (const float*)d_in[2];
    float* out        = (float*)d_out;

    const int N = in_sizes[2];          // 4096
    const int K = in_sizes[1] / N;      // 4096
    const int M = in_sizes[0] / K;      // 8192

    quant_w_kernel<<<N, 256>>>(w, K);
    quant_x_kernel<<<M, 256>>>(x, K);

    dim3 grid(N / 128, M / 128);
    gemm_kernel<<<grid, 256>>>(out, bias, M, N, K);
}

// round 6
// speedup vs baseline: 3.3711x; 3.3711x over previous
#include <cuda_runtime.h>
#include <cuda_fp16.h>
#include <cstdint>

// =====================================================================
// QuantLinear W8A8 — fp16 mma.sync probe.
//   A = (Xq - zp[m])  exact integers in fp16 (|.| <= ~510)
//   B = Wq            exact integers in fp16 (|.| <= 127)
//   acc = A @ B^T in fp32 (HMMA), Y = acc * sa[m]*sw[n] + bias[n]
// GEMM geometry identical to the verified int8 R2 kernel (64B smem
// rows, 16B-chunk swizzle, same ldmatrix lane mapping), with
// m16n8k16.f32.f16.f16.f32 replacing the int8 mma.
// =====================================================================

static constexpr int M_MAX = 8192;
static constexpr int N_MAX = 4096;
static constexpr int K_MAX = 4096;

__device__ __half g_xh[(size_t)M_MAX * K_MAX];   // Xq - zp
__device__ __half g_wh[(size_t)N_MAX * K_MAX];   // Wq
__device__ float  g_ascale[M_MAX];
__device__ float  g_wscale[N_MAX];

// ======================= PTX helpers =======================

__device__ __forceinline__ uint32_t smem_to_u32(const void* p) {
    uint32_t a;
    asm("{ .reg .u64 t; cvta.to.shared.u64 t, %1; cvt.u32.u64 %0, t; }"
        : "=r"(a) : "l"(p));
    return a;
}

__device__ __forceinline__ void cp_async16(uint32_t smem_addr, const void* gptr) {
    asm volatile("cp.async.cg.shared.global [%0], [%1], 16;\n"
                 :: "r"(smem_addr), "l"(gptr) : "memory");
}

#define CP_ASYNC_COMMIT() asm volatile("cp.async.commit_group;\n" ::: "memory")
#define CP_ASYNC_WAIT(n)  asm volatile("cp.async.wait_group %0;\n" :: "n"(n) : "memory")

__device__ __forceinline__ void ldmatrix_x4(uint32_t& r0, uint32_t& r1,
                                            uint32_t& r2, uint32_t& r3,
                                            uint32_t addr) {
    asm volatile("ldmatrix.sync.aligned.m8n8.x4.shared.b16 {%0,%1,%2,%3}, [%4];"
                 : "=r"(r0), "=r"(r1), "=r"(r2), "=r"(r3) : "r"(addr));
}

__device__ __forceinline__ void hmma16816(float& c0, float& c1, float& c2, float& c3,
                                          uint32_t a0, uint32_t a1, uint32_t a2, uint32_t a3,
                                          uint32_t b0, uint32_t b1) {
    asm volatile(
        "mma.sync.aligned.m16n8k16.row.col.f32.f16.f16.f32 "
        "{%0,%1,%2,%3}, {%4,%5,%6,%7}, {%8,%9}, {%0,%1,%2,%3};"
        : "+f"(c0), "+f"(c1), "+f"(c2), "+f"(c3)
        : "r"(a0), "r"(a1), "r"(a2), "r"(a3), "r"(b0), "r"(b1));
}

// ======================= quantization kernels =======================

__global__ void __launch_bounds__(256) quant_w_kernel(const float* __restrict__ w, int K) {
    const int n = blockIdx.x;
    const float4* row = reinterpret_cast<const float4*>(w + (size_t)n * K);
    const int nv = K >> 2;

    float amax = 0.0f;
    for (int i = threadIdx.x; i < nv; i += blockDim.x) {
        float4 v = row[i];
        amax = fmaxf(amax, fmaxf(fmaxf(fabsf(v.x), fabsf(v.y)),
                                 fmaxf(fabsf(v.z), fabsf(v.w))));
    }
    #pragma unroll
    for (int o = 16; o; o >>= 1)
        amax = fmaxf(amax, __shfl_xor_sync(0xFFFFFFFF, amax, o));

    __shared__ float s_amax[8];
    __shared__ float s_inv;
    const int wid = threadIdx.x >> 5;
    if ((threadIdx.x & 31) == 0) s_amax[wid] = amax;
    __syncthreads();
    if (threadIdx.x == 0) {
        float a = s_amax[0];
        #pragma unroll
        for (int i = 1; i < 8; i++) a = fmaxf(a, s_amax[i]);
        float sc = (a > 0.0f) ? __fdiv_rn(a, 127.0f) : 1.0f;
        g_wscale[n] = sc;
        s_inv = __fdiv_rn(1.0f, sc);
    }
    __syncthreads();
    const float inv = s_inv;

    __half2* dst = reinterpret_cast<__half2*>(g_wh + (size_t)n * K);
    for (int i = threadIdx.x; i < nv; i += blockDim.x) {
        float4 v = row[i];
        float q0 = fminf(fmaxf(rintf(v.x * inv), -127.0f), 127.0f);
        float q1 = fminf(fmaxf(rintf(v.y * inv), -127.0f), 127.0f);
        float q2 = fminf(fmaxf(rintf(v.z * inv), -127.0f), 127.0f);
        float q3 = fminf(fmaxf(rintf(v.w * inv), -127.0f), 127.0f);
        dst[2 * i]     = __floats2half2_rn(q0, q1);
        dst[2 * i + 1] = __floats2half2_rn(q2, q3);
    }
}

__global__ void __launch_bounds__(256) quant_x_kernel(const float* __restrict__ x, int K) {
    const int m = blockIdx.x;
    const float4* row = reinterpret_cast<const float4*>(x + (size_t)m * K);
    const int nv = K >> 2;

    float vmin = 3.0e38f, vmax = -3.0e38f;
    for (int i = threadIdx.x; i < nv; i += blockDim.x) {
        float4 v = row[i];
        vmin = fminf(vmin, fminf(fminf(v.x, v.y), fminf(v.z, v.w)));
        vmax = fmaxf(vmax, fmaxf(fmaxf(v.x, v.y), fmaxf(v.z, v.w)));
    }
    #pragma unroll
    for (int o = 16; o; o >>= 1) {
        vmin = fminf(vmin, __shfl_xor_sync(0xFFFFFFFF, vmin, o));
        vmax = fmaxf(vmax, __shfl_xor_sync(0xFFFFFFFF, vmax, o));
    }
    __shared__ float s_min[8], s_max[8];
    __shared__ float s_inv, s_zp;
    const int wid = threadIdx.x >> 5;
    if ((threadIdx.x & 31) == 0) { s_min[wid] = vmin; s_max[wid] = vmax; }
    __syncthreads();
    if (threadIdx.x == 0) {
        float mn = s_min[0], mx = s_max[0];
        #pragma unroll
        for (int i = 1; i < 8; i++) { mn = fminf(mn, s_min[i]); mx = fmaxf(mx, s_max[i]); }
        float rng = mx - mn;
        float sc = (rng > 0.0f) ? __fdiv_rn(rng, 255.0f) : 1.0f;
        float zp = rintf(__fdiv_rn(-mn, sc));
        g_ascale[m] = sc;
        s_inv = __fdiv_rn(1.0f, sc);
        s_zp = zp;
    }
    __syncthreads();
    const float inv = s_inv, zp = s_zp;

    __half2* dst = reinterpret_cast<__half2*>(g_xh + (size_t)m * K);
    for (int i = threadIdx.x; i < nv; i += blockDim.x) {
        float4 v = row[i];
        // Xd = clip(round(x/s)+zp, 0, 255) - zp  (exact small integer)
        float q0 = fminf(fmaxf(rintf(v.x * inv) + zp, 0.0f), 255.0f) - zp;
        float q1 = fminf(fmaxf(rintf(v.y * inv) + zp, 0.0f), 255.0f) - zp;
        float q2 = fminf(fmaxf(rintf(v.z * inv) + zp, 0.0f), 255.0f) - zp;
        float q3 = fminf(fmaxf(rintf(v.w * inv) + zp, 0.0f), 255.0f) - zp;
        dst[2 * i]     = __floats2half2_rn(q0, q1);
        dst[2 * i + 1] = __floats2half2_rn(q2, q3);
    }
}

// ======================= fp16 GEMM kernel =======================
// CTA 128(M) x 128(N), 256 threads = 8 warps (2x4), warp tile 64x32.
// K-chunk = 32 halfs = 64B smem row; 2 k16 steps per chunk.
// 3-stage cp.async pipeline; 16B-chunk swizzle: cs = c ^ ((row>>1)&3).

static constexpr int STAGES = 3;
static constexpr int STAGE_BYTES = 16384;  // A 8K + B 8K
static constexpr int SMEM_BYTES = STAGES * STAGE_BYTES;

__global__ void __launch_bounds__(256)
gemm_kernel(float* __restrict__ out, const float* __restrict__ bias,
            int M, int N, int K) {
    __shared__ __align__(1024) uint8_t smem[SMEM_BYTES];
    const uint32_t smem_u32 = smem_to_u32(smem);

    const int tid  = threadIdx.x;
    const int lane = tid & 31;
    const int wid  = tid >> 5;
    const int m0 = blockIdx.y * 128;
    const int n0 = blockIdx.x * 128;
    const int warp_m = (wid >> 2) * 64;
    const int warp_n = (wid & 3) * 32;

    const size_t Kb = (size_t)K * 2;       // row stride in bytes
    const int KT = K >> 5;                 // 32-half chunks

    const uint8_t* gA = reinterpret_cast<const uint8_t*>(g_xh) + (size_t)m0 * Kb;
    const uint8_t* gB = reinterpret_cast<const uint8_t*>(g_wh) + (size_t)n0 * Kb;

    const int cr0 = tid >> 2, cc0 = tid & 3;
    const int cswz0 = cc0 ^ ((cr0 >> 1) & 3);
    const int cr1 = (tid + 256) >> 2, cc1 = cc0;
    const int cswz1 = cc1 ^ ((cr1 >> 1) & 3);

    auto issue_stage = [&](int kt, int s) {
        if (kt < KT) {
            uint32_t sa = smem_u32 + s * STAGE_BYTES;
            uint32_t sb = sa + 8192;
            const uint8_t* ga = gA + (size_t)kt * 64;
            const uint8_t* gb = gB + (size_t)kt * 64;
            cp_async16(sa + cr0 * 64 + (cswz0 << 4), ga + (size_t)cr0 * Kb + cc0 * 16);
            cp_async16(sb + cr0 * 64 + (cswz0 << 4), gb + (size_t)cr0 * Kb + cc0 * 16);
            cp_async16(sa + cr1 * 64 + (cswz1 << 4), ga + (size_t)cr1 * Kb + cc1 * 16);
            cp_async16(sb + cr1 * 64 + (cswz1 << 4), gb + (size_t)cr1 * Kb + cc1 * 16);
        }
        CP_ASYNC_COMMIT();
    };

    // ldmatrix lane geometry (same chunk structure verified in R2)
    const int a_row = lane & 15;
    const int a_cs  = lane >> 4;
    const int a_swz = (a_row >> 1) & 3;
    const int b_row = (lane & 7) + ((lane >> 4) << 3);
    const int b_cs  = (lane >> 3) & 1;
    const int b_swz = (b_row >> 1) & 3;

    float acc[4][4][4];
    #pragma unroll
    for (int i = 0; i < 4; i++)
        #pragma unroll
        for (int j = 0; j < 4; j++)
            #pragma unroll
            for (int r = 0; r < 4; r++) acc[i][j][r] = 0.0f;

    #pragma unroll
    for (int s = 0; s < STAGES - 1; s++) issue_stage(s, s);

    for (int kt = 0; kt < KT; kt++) {
        CP_ASYNC_WAIT(STAGES - 2);
        __syncthreads();

        issue_stage(kt + STAGES - 1, (kt + STAGES - 1) % STAGES);

        const int s = kt % STAGES;
        const uint32_t sa = smem_u32 + s * STAGE_BYTES;
        const uint32_t sb = sa + 8192;

        #pragma unroll
        for (int ks = 0; ks < 2; ks++) {   // two k16 steps per 64B chunk
            uint32_t af[4][4];
            #pragma unroll
            for (int mf = 0; mf < 4; mf++) {
                uint32_t addr = sa + (warp_m + mf * 16 + a_row) * 64
                              + (((2 * ks + a_cs) ^ a_swz) << 4);
                ldmatrix_x4(af[mf][0], af[mf][1], af[mf][2], af[mf][3], addr);
            }
            uint32_t bf[2][4];
            #pragma unroll
            for (int p = 0; p < 2; p++) {
                uint32_t addr = sb + (warp_n + p * 16 + b_row) * 64
                              + (((2 * ks + b_cs) ^ b_swz) << 4);
                ldmatrix_x4(bf[p][0], bf[p][1], bf[p][2], bf[p][3], addr);
            }
            #pragma unroll
            for (int mf = 0; mf < 4; mf++) {
                #pragma unroll
                for (int nf = 0; nf < 4; nf++) {
                    const int p = nf >> 1, h = (nf & 1) << 1;
                    hmma16816(acc[mf][nf][0], acc[mf][nf][1],
                              acc[mf][nf][2], acc[mf][nf][3],
                              af[mf][0], af[mf][1], af[mf][2], af[mf][3],
                              bf[p][h], bf[p][h + 1]);
                }
            }
        }
    }

    // ================= epilogue: Y = acc*sa*sw + bias =================
    #pragma unroll
    for (int mf = 0; mf < 4; mf++) {
        const int gr0 = m0 + warp_m + mf * 16 + (lane >> 2);
        const int gr1 = gr0 + 8;
        const float sa0 = g_ascale[gr0];
        const float sa1 = g_ascale[gr1];
        #pragma unroll
        for (int nf = 0; nf < 4; nf++) {
            const int gc = n0 + warp_n + nf * 8 + 2 * (lane & 3);
            const float sw0 = g_wscale[gc], sw1 = g_wscale[gc + 1];
            const float bb0 = bias[gc],     bb1 = bias[gc + 1];
            float2 v0, v1;
            v0.x = acc[mf][nf][0] * (sa0 * sw0) + bb0;
            v0.y = acc[mf][nf][1] * (sa0 * sw1) + bb1;
            v1.x = acc[mf][nf][2] * (sa1 * sw0) + bb0;
            v1.y = acc[mf][nf][3] * (sa1 * sw1) + bb1;
            *reinterpret_cast<float2*>(out + (size_t)gr0 * N + gc) = v0;
            *reinterpret_cast<float2*>(out + (size_t)gr1 * N + gc) = v1;
        }
    }
}

// ======================= launch =======================

extern "C" void kernel_launch(void* const* d_in, const int* in_sizes, int n_in,
                              void* d_out, int out_size) {
    const float* x    = (const float*)d_in[0];
    const float* w    = (const float*)d_in[1];
    const float* bias = (const float*)d_in[2];
    float* out        = (float*)d_out;

    const int N = in_sizes[2];          // 4096
    const int K = in_sizes[1] / N;      // 4096
    const int M = in_sizes[0] / K;      // 8192

    quant_w_kernel<<<N, 256>>>(w, K);
    quant_x_kernel<<<M, 256>>>(x, K);

    dim3 grid(N / 128, M / 128);
    gemm_kernel<<<grid, 256>>>(out, bias, M, N, K);
}

// round 7
// speedup vs baseline: 3.6776x; 1.0909x over previous
#include <cuda_runtime.h>
#include <cuda_fp16.h>
#include <cstdint>

// =====================================================================
// QuantLinear W8A8 — fp16 legacy-HMMA GEMM (mma.sync m16n8k16), v2.
//   A = (Xq - zp[m])  exact integers in fp16; B = Wq exact in fp16
//   acc = A @ B^T (fp32), Y = acc * sa[m]*sw[n] + bias[n]
// GEMM v2: CTA 128x128, 4 warps (64x64 each), BK=64 halfs = 128B rows,
// full XOR-8 swizzle (conflict-free ldmatrix), 3-stage cp.async,
// 96KB dynamic smem -> 2 CTAs/SM.
// =====================================================================

static constexpr int M_MAX = 8192;
static constexpr int N_MAX = 4096;
static constexpr int K_MAX = 4096;

__device__ __half g_xh[(size_t)M_MAX * K_MAX];   // Xq - zp
__device__ __half g_wh[(size_t)N_MAX * K_MAX];   // Wq
__device__ float  g_ascale[M_MAX];
__device__ float  g_wscale[N_MAX];

// ======================= PTX helpers =======================

__device__ __forceinline__ uint32_t smem_to_u32(const void* p) {
    uint32_t a;
    asm("{ .reg .u64 t; cvta.to.shared.u64 t, %1; cvt.u32.u64 %0, t; }"
        : "=r"(a) : "l"(p));
    return a;
}

__device__ __forceinline__ void cp_async16(uint32_t smem_addr, const void* gptr) {
    asm volatile("cp.async.cg.shared.global [%0], [%1], 16;\n"
                 :: "r"(smem_addr), "l"(gptr) : "memory");
}

#define CP_ASYNC_COMMIT() asm volatile("cp.async.commit_group;\n" ::: "memory")
#define CP_ASYNC_WAIT(n)  asm volatile("cp.async.wait_group %0;\n" :: "n"(n) : "memory")

__device__ __forceinline__ void ldmatrix_x4(uint32_t& r0, uint32_t& r1,
                                            uint32_t& r2, uint32_t& r3,
                                            uint32_t addr) {
    asm volatile("ldmatrix.sync.aligned.m8n8.x4.shared.b16 {%0,%1,%2,%3}, [%4];"
                 : "=r"(r0), "=r"(r1), "=r"(r2), "=r"(r3) : "r"(addr));
}

__device__ __forceinline__ void hmma16816(float& c0, float& c1, float& c2, float& c3,
                                          uint32_t a0, uint32_t a1, uint32_t a2, uint32_t a3,
                                          uint32_t b0, uint32_t b1) {
    asm volatile(
        "mma.sync.aligned.m16n8k16.row.col.f32.f16.f16.f32 "
        "{%0,%1,%2,%3}, {%4,%5,%6,%7}, {%8,%9}, {%0,%1,%2,%3};"
        : "+f"(c0), "+f"(c1), "+f"(c2), "+f"(c3)
        : "r"(a0), "r"(a1), "r"(a2), "r"(a3), "r"(b0), "r"(b1));
}

// ======================= quantization kernels =======================

__global__ void __launch_bounds__(256) quant_w_kernel(const float* __restrict__ w, int K) {
    const int n = blockIdx.x;
    const float4* row = reinterpret_cast<const float4*>(w + (size_t)n * K);
    const int nv = K >> 2;

    float amax = 0.0f;
    for (int i = threadIdx.x; i < nv; i += blockDim.x) {
        float4 v = row[i];
        amax = fmaxf(amax, fmaxf(fmaxf(fabsf(v.x), fabsf(v.y)),
                                 fmaxf(fabsf(v.z), fabsf(v.w))));
    }
    #pragma unroll
    for (int o = 16; o; o >>= 1)
        amax = fmaxf(amax, __shfl_xor_sync(0xFFFFFFFF, amax, o));

    __shared__ float s_amax[8];
    __shared__ float s_inv;
    const int wid = threadIdx.x >> 5;
    if ((threadIdx.x & 31) == 0) s_amax[wid] = amax;
    __syncthreads();
    if (threadIdx.x == 0) {
        float a = s_amax[0];
        #pragma unroll
        for (int i = 1; i < 8; i++) a = fmaxf(a, s_amax[i]);
        float sc = (a > 0.0f) ? __fdiv_rn(a, 127.0f) : 1.0f;
        g_wscale[n] = sc;
        s_inv = __fdiv_rn(1.0f, sc);
    }
    __syncthreads();
    const float inv = s_inv;

    __half2* dst = reinterpret_cast<__half2*>(g_wh + (size_t)n * K);
    for (int i = threadIdx.x; i < nv; i += blockDim.x) {
        float4 v = row[i];
        float q0 = fminf(fmaxf(rintf(v.x * inv), -127.0f), 127.0f);
        float q1 = fminf(fmaxf(rintf(v.y * inv), -127.0f), 127.0f);
        float q2 = fminf(fmaxf(rintf(v.z * inv), -127.0f), 127.0f);
        float q3 = fminf(fmaxf(rintf(v.w * inv), -127.0f), 127.0f);
        dst[2 * i]     = __floats2half2_rn(q0, q1);
        dst[2 * i + 1] = __floats2half2_rn(q2, q3);
    }
}

__global__ void __launch_bounds__(256) quant_x_kernel(const float* __restrict__ x, int K) {
    const int m = blockIdx.x;
    const float4* row = reinterpret_cast<const float4*>(x + (size_t)m * K);
    const int nv = K >> 2;

    float vmin = 3.0e38f, vmax = -3.0e38f;
    for (int i = threadIdx.x; i < nv; i += blockDim.x) {
        float4 v = row[i];
        vmin = fminf(vmin, fminf(fminf(v.x, v.y), fminf(v.z, v.w)));
        vmax = fmaxf(vmax, fmaxf(fmaxf(v.x, v.y), fmaxf(v.z, v.w)));
    }
    #pragma unroll
    for (int o = 16; o; o >>= 1) {
        vmin = fminf(vmin, __shfl_xor_sync(0xFFFFFFFF, vmin, o));
        vmax = fmaxf(vmax, __shfl_xor_sync(0xFFFFFFFF, vmax, o));
    }
    __shared__ float s_min[8], s_max[8];
    __shared__ float s_inv, s_zp;
    const int wid = threadIdx.x >> 5;
    if ((threadIdx.x & 31) == 0) { s_min[wid] = vmin; s_max[wid] = vmax; }
    __syncthreads();
    if (threadIdx.x == 0) {
        float mn = s_min[0], mx = s_max[0];
        #pragma unroll
        for (int i = 1; i < 8; i++) { mn = fminf(mn, s_min[i]); mx = fmaxf(mx, s_max[i]); }
        float rng = mx - mn;
        float sc = (rng > 0.0f) ? __fdiv_rn(rng, 255.0f) : 1.0f;
        float zp = rintf(__fdiv_rn(-mn, sc));
        g_ascale[m] = sc;
        s_inv = __fdiv_rn(1.0f, sc);
        s_zp = zp;
    }
    __syncthreads();
    const float inv = s_inv, zp = s_zp;

    __half2* dst = reinterpret_cast<__half2*>(g_xh + (size_t)m * K);
    for (int i = threadIdx.x; i < nv; i += blockDim.x) {
        float4 v = row[i];
        float q0 = fminf(fmaxf(rintf(v.x * inv) + zp, 0.0f), 255.0f) - zp;
        float q1 = fminf(fmaxf(rintf(v.y * inv) + zp, 0.0f), 255.0f) - zp;
        float q2 = fminf(fmaxf(rintf(v.z * inv) + zp, 0.0f), 255.0f) - zp;
        float q3 = fminf(fmaxf(rintf(v.w * inv) + zp, 0.0f), 255.0f) - zp;
        dst[2 * i]     = __floats2half2_rn(q0, q1);
        dst[2 * i + 1] = __floats2half2_rn(q2, q3);
    }
}

// ======================= fp16 GEMM kernel v2 =======================
// CTA 128x128, 128 threads = 4 warps in 2x2, warp tile 64x64.
// BK = 64 halfs = 128B smem rows, 8 x 16B chunks, swizzle c ^ (row&7)
// -> conflict-free ldmatrix. 3-stage cp.async, 96KB dynamic smem.

static constexpr int STAGES = 3;
static constexpr int STAGE_BYTES = 32768;                 // A 16K + B 16K
static constexpr int GEMM_SMEM = STAGES * STAGE_BYTES;    // 96KB

__global__ void __launch_bounds__(128)
gemm_kernel(float* __restrict__ out, const float* __restrict__ bias,
            int M, int N, int K) {
    extern __shared__ __align__(1024) uint8_t smem[];
    const uint32_t smem_u32 = smem_to_u32(smem);

    const int tid  = threadIdx.x;
    const int lane = tid & 31;
    const int wid  = tid >> 5;
    const int m0 = blockIdx.y * 128;
    const int n0 = blockIdx.x * 128;
    const int warp_m = (wid >> 1) * 64;   // 0 or 64
    const int warp_n = (wid & 1) * 64;    // 0 or 64

    const size_t Kb = (size_t)K * 2;      // row stride in bytes
    const int KT = K >> 6;                // 64-half (128B) chunks

    const uint8_t* gA = reinterpret_cast<const uint8_t*>(g_xh) + (size_t)m0 * Kb;
    const uint8_t* gB = reinterpret_cast<const uint8_t*>(g_wh) + (size_t)n0 * Kb;

    // copy: per tile 128 rows x 8 chunks of 16B; 128 threads x 8 chunks
    auto issue_stage = [&](int kt, int s) {
        if (kt < KT) {
            uint32_t sa = smem_u32 + s * STAGE_BYTES;
            uint32_t sb = sa + 16384;
            const uint8_t* ga = gA + (size_t)kt * 128;
            const uint8_t* gb = gB + (size_t)kt * 128;
            #pragma unroll
            for (int j = 0; j < 8; j++) {
                int idx = tid + j * 128;      // 0..1023
                int row = idx >> 3;           // 0..127
                int c   = idx & 7;
                int cs  = c ^ (row & 7);
                cp_async16(sa + row * 128 + (cs << 4), ga + (size_t)row * Kb + c * 16);
                cp_async16(sb + row * 128 + (cs << 4), gb + (size_t)row * Kb + c * 16);
            }
        }
        CP_ASYNC_COMMIT();
    };

    // ldmatrix lane geometry; swizzle uses (row & 7) (tile offsets are mult of 16)
    const int a_row = lane & 15;
    const int a_cs  = lane >> 4;
    const int a_swz = a_row & 7;
    const int b_row = (lane & 7) + ((lane >> 4) << 3);
    const int b_cs  = (lane >> 3) & 1;
    const int b_swz = b_row & 7;

    float acc[4][8][4];
    #pragma unroll
    for (int i = 0; i < 4; i++)
        #pragma unroll
        for (int j = 0; j < 8; j++)
            #pragma unroll
            for (int r = 0; r < 4; r++) acc[i][j][r] = 0.0f;

    #pragma unroll
    for (int s = 0; s < STAGES - 1; s++) issue_stage(s, s);

    for (int kt = 0; kt < KT; kt++) {
        CP_ASYNC_WAIT(STAGES - 2);
        __syncthreads();

        issue_stage(kt + STAGES - 1, (kt + STAGES - 1) % STAGES);

        const int s = kt % STAGES;
        const uint32_t sa = smem_u32 + s * STAGE_BYTES;
        const uint32_t sb = sa + 16384;

        #pragma unroll
        for (int ks = 0; ks < 4; ks++) {    // 4 x k16 per 128B chunk
            uint32_t af[4][4];
            #pragma unroll
            for (int mf = 0; mf < 4; mf++) {
                uint32_t addr = sa + (warp_m + mf * 16 + a_row) * 128
                              + (((2 * ks + a_cs) ^ a_swz) << 4);
                ldmatrix_x4(af[mf][0], af[mf][1], af[mf][2], af[mf][3], addr);
            }
            uint32_t bf[4][4];
            #pragma unroll
            for (int p = 0; p < 4; p++) {
                uint32_t addr = sb + (warp_n + p * 16 + b_row) * 128
                              + (((2 * ks + b_cs) ^ b_swz) << 4);
                ldmatrix_x4(bf[p][0], bf[p][1], bf[p][2], bf[p][3], addr);
            }
            #pragma unroll
            for (int mf = 0; mf < 4; mf++) {
                #pragma unroll
                for (int nf = 0; nf < 8; nf++) {
                    const int p = nf >> 1, h = (nf & 1) << 1;
                    hmma16816(acc[mf][nf][0], acc[mf][nf][1],
                              acc[mf][nf][2], acc[mf][nf][3],
                              af[mf][0], af[mf][1], af[mf][2], af[mf][3],
                              bf[p][h], bf[p][h + 1]);
                }
            }
        }
    }

    // ================= epilogue: Y = acc*sa*sw + bias =================
    #pragma unroll
    for (int mf = 0; mf < 4; mf++) {
        const int gr0 = m0 + warp_m + mf * 16 + (lane >> 2);
        const int gr1 = gr0 + 8;
        const float sa0 = g_ascale[gr0];
        const float sa1 = g_ascale[gr1];
        #pragma unroll
        for (int nf = 0; nf < 8; nf++) {
            const int gc = n0 + warp_n + nf * 8 + 2 * (lane & 3);
            const float sw0 = g_wscale[gc], sw1 = g_wscale[gc + 1];
            const float bb0 = bias[gc],     bb1 = bias[gc + 1];
            float2 v0, v1;
            v0.x = acc[mf][nf][0] * (sa0 * sw0) + bb0;
            v0.y = acc[mf][nf][1] * (sa0 * sw1) + bb1;
            v1.x = acc[mf][nf][2] * (sa1 * sw0) + bb0;
            v1.y = acc[mf][nf][3] * (sa1 * sw1) + bb1;
            *reinterpret_cast<float2*>(out + (size_t)gr0 * N + gc) = v0;
            *reinterpret_cast<float2*>(out + (size_t)gr1 * N + gc) = v1;
        }
    }
}

// ======================= launch =======================

extern "C" void kernel_launch(void* const* d_in, const int* in_sizes, int n_in,
                              void* d_out, int out_size) {
    const float* x    = (const float*)d_in[0];
    const float* w    = (const float*)d_in[1];
    const float* bias = (const float*)d_in[2];
    float* out        = (float*)d_out;

    const int N = in_sizes[2];          // 4096
    const int K = in_sizes[1] / N;      // 4096
    const int M = in_sizes[0] / K;      // 8192

    cudaFuncSetAttribute(gemm_kernel,
                         cudaFuncAttributeMaxDynamicSharedMemorySize, GEMM_SMEM);

    quant_w_kernel<<<N, 256>>>(w, K);
    quant_x_kernel<<<M, 256>>>(x, K);

    dim3 grid(N / 128, M / 128);
    gemm_kernel<<<grid, 128, GEMM_SMEM>>>(out, bias, M, N, K);
}

// round 8
// speedup vs baseline: 4.2634x; 1.1593x over previous
#include <cuda_runtime.h>
#include <cuda_fp16.h>
#include <cstdint>

// =====================================================================
// QuantLinear W8A8 — fp16 legacy-HMMA GEMM (mma.sync m16n8k16), v3.
//   A = (Xq - zp[m]) exact in fp16; B = Wq exact in fp16
//   acc = A @ B^T (fp32), Y = acc * sa[m]*sw[n] + bias[n]
// v3: register double-buffered fragments (LDSM prefetched one k16
// step ahead of HMMA), cp.async issued after first frag loads.
// CTA 128x128, 4 warps (64x64), BK=64, XOR-8 swizzle, 3 stages, 96KB.
// =====================================================================

static constexpr int M_MAX = 8192;
static constexpr int N_MAX = 4096;
static constexpr int K_MAX = 4096;

__device__ __half g_xh[(size_t)M_MAX * K_MAX];   // Xq - zp
__device__ __half g_wh[(size_t)N_MAX * K_MAX];   // Wq
__device__ float  g_ascale[M_MAX];
__device__ float  g_wscale[N_MAX];

// ======================= PTX helpers =======================

__device__ __forceinline__ uint32_t smem_to_u32(const void* p) {
    uint32_t a;
    asm("{ .reg .u64 t; cvta.to.shared.u64 t, %1; cvt.u32.u64 %0, t; }"
        : "=r"(a) : "l"(p));
    return a;
}

__device__ __forceinline__ void cp_async16(uint32_t smem_addr, const void* gptr) {
    asm volatile("cp.async.cg.shared.global [%0], [%1], 16;\n"
                 :: "r"(smem_addr), "l"(gptr) : "memory");
}

#define CP_ASYNC_COMMIT() asm volatile("cp.async.commit_group;\n" ::: "memory")
#define CP_ASYNC_WAIT(n)  asm volatile("cp.async.wait_group %0;\n" :: "n"(n) : "memory")

__device__ __forceinline__ void ldmatrix_x4(uint32_t& r0, uint32_t& r1,
                                            uint32_t& r2, uint32_t& r3,
                                            uint32_t addr) {
    asm volatile("ldmatrix.sync.aligned.m8n8.x4.shared.b16 {%0,%1,%2,%3}, [%4];"
                 : "=r"(r0), "=r"(r1), "=r"(r2), "=r"(r3) : "r"(addr));
}

__device__ __forceinline__ void hmma16816(float& c0, float& c1, float& c2, float& c3,
                                          uint32_t a0, uint32_t a1, uint32_t a2, uint32_t a3,
                                          uint32_t b0, uint32_t b1) {
    asm volatile(
        "mma.sync.aligned.m16n8k16.row.col.f32.f16.f16.f32 "
        "{%0,%1,%2,%3}, {%4,%5,%6,%7}, {%8,%9}, {%0,%1,%2,%3};"
        : "+f"(c0), "+f"(c1), "+f"(c2), "+f"(c3)
        : "r"(a0), "r"(a1), "r"(a2), "r"(a3), "r"(b0), "r"(b1));
}

// ======================= quantization kernels =======================

__global__ void __launch_bounds__(256) quant_w_kernel(const float* __restrict__ w, int K) {
    const int n = blockIdx.x;
    const float4* row = reinterpret_cast<const float4*>(w + (size_t)n * K);
    const int nv = K >> 2;

    float amax = 0.0f;
    for (int i = threadIdx.x; i < nv; i += blockDim.x) {
        float4 v = row[i];
        amax = fmaxf(amax, fmaxf(fmaxf(fabsf(v.x), fabsf(v.y)),
                                 fmaxf(fabsf(v.z), fabsf(v.w))));
    }
    #pragma unroll
    for (int o = 16; o; o >>= 1)
        amax = fmaxf(amax, __shfl_xor_sync(0xFFFFFFFF, amax, o));

    __shared__ float s_amax[8];
    __shared__ float s_inv;
    const int wid = threadIdx.x >> 5;
    if ((threadIdx.x & 31) == 0) s_amax[wid] = amax;
    __syncthreads();
    if (threadIdx.x == 0) {
        float a = s_amax[0];
        #pragma unroll
        for (int i = 1; i < 8; i++) a = fmaxf(a, s_amax[i]);
        float sc = (a > 0.0f) ? __fdiv_rn(a, 127.0f) : 1.0f;
        g_wscale[n] = sc;
        s_inv = __fdiv_rn(1.0f, sc);
    }
    __syncthreads();
    const float inv = s_inv;

    __half2* dst = reinterpret_cast<__half2*>(g_wh + (size_t)n * K);
    for (int i = threadIdx.x; i < nv; i += blockDim.x) {
        float4 v = row[i];
        float q0 = fminf(fmaxf(rintf(v.x * inv), -127.0f), 127.0f);
        float q1 = fminf(fmaxf(rintf(v.y * inv), -127.0f), 127.0f);
        float q2 = fminf(fmaxf(rintf(v.z * inv), -127.0f), 127.0f);
        float q3 = fminf(fmaxf(rintf(v.w * inv), -127.0f), 127.0f);
        dst[2 * i]     = __floats2half2_rn(q0, q1);
        dst[2 * i + 1] = __floats2half2_rn(q2, q3);
    }
}

__global__ void __launch_bounds__(256) quant_x_kernel(const float* __restrict__ x, int K) {
    const int m = blockIdx.x;
    const float4* row = reinterpret_cast<const float4*>(x + (size_t)m * K);
    const int nv = K >> 2;

    float vmin = 3.0e38f, vmax = -3.0e38f;
    for (int i = threadIdx.x; i < nv; i += blockDim.x) {
        float4 v = row[i];
        vmin = fminf(vmin, fminf(fminf(v.x, v.y), fminf(v.z, v.w)));
        vmax = fmaxf(vmax, fmaxf(fmaxf(v.x, v.y), fmaxf(v.z, v.w)));
    }
    #pragma unroll
    for (int o = 16; o; o >>= 1) {
        vmin = fminf(vmin, __shfl_xor_sync(0xFFFFFFFF, vmin, o));
        vmax = fmaxf(vmax, __shfl_xor_sync(0xFFFFFFFF, vmax, o));
    }
    __shared__ float s_min[8], s_max[8];
    __shared__ float s_inv, s_zp;
    const int wid = threadIdx.x >> 5;
    if ((threadIdx.x & 31) == 0) { s_min[wid] = vmin; s_max[wid] = vmax; }
    __syncthreads();
    if (threadIdx.x == 0) {
        float mn = s_min[0], mx = s_max[0];
        #pragma unroll
        for (int i = 1; i < 8; i++) { mn = fminf(mn, s_min[i]); mx = fmaxf(mx, s_max[i]); }
        float rng = mx - mn;
        float sc = (rng > 0.0f) ? __fdiv_rn(rng, 255.0f) : 1.0f;
        float zp = rintf(__fdiv_rn(-mn, sc));
        g_ascale[m] = sc;
        s_inv = __fdiv_rn(1.0f, sc);
        s_zp = zp;
    }
    __syncthreads();
    const float inv = s_inv, zp = s_zp;

    __half2* dst = reinterpret_cast<__half2*>(g_xh + (size_t)m * K);
    for (int i = threadIdx.x; i < nv; i += blockDim.x) {
        float4 v = row[i];
        float q0 = fminf(fmaxf(rintf(v.x * inv) + zp, 0.0f), 255.0f) - zp;
        float q1 = fminf(fmaxf(rintf(v.y * inv) + zp, 0.0f), 255.0f) - zp;
        float q2 = fminf(fmaxf(rintf(v.z * inv) + zp, 0.0f), 255.0f) - zp;
        float q3 = fminf(fmaxf(rintf(v.w * inv) + zp, 0.0f), 255.0f) - zp;
        dst[2 * i]     = __floats2half2_rn(q0, q1);
        dst[2 * i + 1] = __floats2half2_rn(q2, q3);
    }
}

// ======================= fp16 GEMM kernel v3 =======================

static constexpr int STAGES = 3;
static constexpr int STAGE_BYTES = 32768;                 // A 16K + B 16K
static constexpr int GEMM_SMEM = STAGES * STAGE_BYTES;    // 96KB

__global__ void __launch_bounds__(128)
gemm_kernel(float* __restrict__ out, const float* __restrict__ bias,
            int M, int N, int K) {
    extern __shared__ __align__(1024) uint8_t smem[];
    const uint32_t smem_u32 = smem_to_u32(smem);

    const int tid  = threadIdx.x;
    const int lane = tid & 31;
    const int wid  = tid >> 5;
    const int m0 = blockIdx.y * 128;
    const int n0 = blockIdx.x * 128;
    const int warp_m = (wid >> 1) * 64;
    const int warp_n = (wid & 1) * 64;

    const size_t Kb = (size_t)K * 2;
    const int KT = K >> 6;                // 64-half (128B) chunks

    const uint8_t* gA = reinterpret_cast<const uint8_t*>(g_xh) + (size_t)m0 * Kb;
    const uint8_t* gB = reinterpret_cast<const uint8_t*>(g_wh) + (size_t)n0 * Kb;

    auto issue_stage = [&](int kt, int s) {
        if (kt < KT) {
            uint32_t sa = smem_u32 + s * STAGE_BYTES;
            uint32_t sb = sa + 16384;
            const uint8_t* ga = gA + (size_t)kt * 128;
            const uint8_t* gb = gB + (size_t)kt * 128;
            #pragma unroll
            for (int j = 0; j < 8; j++) {
                int idx = tid + j * 128;
                int row = idx >> 3;
                int c   = idx & 7;
                int cs  = c ^ (row & 7);
                cp_async16(sa + row * 128 + (cs << 4), ga + (size_t)row * Kb + c * 16);
                cp_async16(sb + row * 128 + (cs << 4), gb + (size_t)row * Kb + c * 16);
            }
        }
        CP_ASYNC_COMMIT();
    };

    const int a_row = lane & 15;
    const int a_cs  = lane >> 4;
    const int a_swz = a_row & 7;
    const int b_row = (lane & 7) + ((lane >> 4) << 3);
    const int b_cs  = (lane >> 3) & 1;
    const int b_swz = b_row & 7;

    float acc[4][8][4];
    #pragma unroll
    for (int i = 0; i < 4; i++)
        #pragma unroll
        for (int j = 0; j < 8; j++)
            #pragma unroll
            for (int r = 0; r < 4; r++) acc[i][j][r] = 0.0f;

    uint32_t af[2][4][4];   // double-buffered fragments
    uint32_t bf[2][4][4];

    auto load_frags = [&](uint32_t sa, uint32_t sb, int ks, int buf) {
        #pragma unroll
        for (int mf = 0; mf < 4; mf++) {
            uint32_t addr = sa + (warp_m + mf * 16 + a_row) * 128
                          + (((2 * ks + a_cs) ^ a_swz) << 4);
            ldmatrix_x4(af[buf][mf][0], af[buf][mf][1],
                        af[buf][mf][2], af[buf][mf][3], addr);
        }
        #pragma unroll
        for (int p = 0; p < 4; p++) {
            uint32_t addr = sb + (warp_n + p * 16 + b_row) * 128
                          + (((2 * ks + b_cs) ^ b_swz) << 4);
            ldmatrix_x4(bf[buf][p][0], bf[buf][p][1],
                        bf[buf][p][2], bf[buf][p][3], addr);
        }
    };

    auto compute = [&](int buf) {
        #pragma unroll
        for (int mf = 0; mf < 4; mf++) {
            #pragma unroll
            for (int nf = 0; nf < 8; nf++) {
                const int p = nf >> 1, h = (nf & 1) << 1;
                hmma16816(acc[mf][nf][0], acc[mf][nf][1],
                          acc[mf][nf][2], acc[mf][nf][3],
                          af[buf][mf][0], af[buf][mf][1],
                          af[buf][mf][2], af[buf][mf][3],
                          bf[buf][p][h], bf[buf][p][h + 1]);
            }
        }
    };

    #pragma unroll
    for (int s = 0; s < STAGES - 1; s++) issue_stage(s, s);

    for (int kt = 0; kt < KT; kt++) {
        CP_ASYNC_WAIT(STAGES - 2);
        __syncthreads();

        const int s = kt % STAGES;
        const uint32_t sa = smem_u32 + s * STAGE_BYTES;
        const uint32_t sb = sa + 16384;

        // load first fragments before issuing the LDGSTS burst
        load_frags(sa, sb, 0, 0);
        issue_stage(kt + STAGES - 1, (kt + STAGES - 1) % STAGES);

        #pragma unroll
        for (int ks = 0; ks < 4; ks++) {
            if (ks < 3) load_frags(sa, sb, ks + 1, (ks + 1) & 1);
            compute(ks & 1);
        }
    }

    // ================= epilogue =================
    #pragma unroll
    for (int mf = 0; mf < 4; mf++) {
        const int gr0 = m0 + warp_m + mf * 16 + (lane >> 2);
        const int gr1 = gr0 + 8;
        const float sa0 = g_ascale[gr0];
        const float sa1 = g_ascale[gr1];
        #pragma unroll
        for (int nf = 0; nf < 8; nf++) {
            const int gc = n0 + warp_n + nf * 8 + 2 * (lane & 3);
            const float sw0 = g_wscale[gc], sw1 = g_wscale[gc + 1];
            const float bb0 = bias[gc],     bb1 = bias[gc + 1];
            float2 v0, v1;
            v0.x = acc[mf][nf][0] * (sa0 * sw0) + bb0;
            v0.y = acc[mf][nf][1] * (sa0 * sw1) + bb1;
            v1.x = acc[mf][nf][2] * (sa1 * sw0) + bb0;
            v1.y = acc[mf][nf][3] * (sa1 * sw1) + bb1;
            *reinterpret_cast<float2*>(out + (size_t)gr0 * N + gc) = v0;
            *reinterpret_cast<float2*>(out + (size_t)gr1 * N + gc) = v1;
        }
    }
}

// ======================= launch =======================

extern "C" void kernel_launch(void* const* d_in, const int* in_sizes, int n_in,
                              void* d_out, int out_size) {
    const float* x    = (const float*)d_in[0];
    const float* w    = (const float*)d_in[1];
    const float* bias = (const float*)d_in[2];
    float* out        = (float*)d_out;

    const int N = in_sizes[2];          // 4096
    const int K = in_sizes[1] / N;      // 4096
    const int M = in_sizes[0] / K;      // 8192

    cudaFuncSetAttribute(gemm_kernel,
                         cudaFuncAttributeMaxDynamicSharedMemorySize, GEMM_SMEM);

    quant_w_kernel<<<N, 256>>>(w, K);
    quant_x_kernel<<<M, 256>>>(x, K);

    dim3 grid(N / 128, M / 128);
    gemm_kernel<<<grid, 128, GEMM_SMEM>>>(out, bias, M, N, K);
}

// round 10
// speedup vs baseline: 4.2843x; 1.0049x over previous
#include <cuda_runtime.h>
#include <cuda_fp16.h>
#include <cstdint>

// =====================================================================
// QuantLinear W8A8 — fp16 legacy-HMMA GEMM (mma.sync m16n8k16), v4.
//   A = (Xq - zp[m]) exact in fp16; B = Wq exact in fp16
//   acc = A @ B^T (fp32), Y = acc * sa[m]*sw[n] + bias[n]
// v4: cp.async burst spread across ks steps (uniform LSU pressure);
// single-pass register-resident quant kernels.
// GEMM: CTA 128x128, 4 warps (64x64), BK=64, XOR-8 swizzle, 3 stages.
// =====================================================================

static constexpr int M_MAX = 8192;
static constexpr int N_MAX = 4096;
static constexpr int K_MAX = 4096;

__device__ __half g_xh[(size_t)M_MAX * K_MAX];   // Xq - zp
__device__ __half g_wh[(size_t)N_MAX * K_MAX];   // Wq
__device__ float  g_ascale[M_MAX];
__device__ float  g_wscale[N_MAX];

// ======================= PTX helpers =======================

__device__ __forceinline__ uint32_t smem_to_u32(const void* p) {
    uint32_t a;
    asm("{ .reg .u64 t; cvta.to.shared.u64 t, %1; cvt.u32.u64 %0, t; }"
        : "=r"(a) : "l"(p));
    return a;
}

__device__ __forceinline__ void cp_async16(uint32_t smem_addr, const void* gptr) {
    asm volatile("cp.async.cg.shared.global [%0], [%1], 16;\n"
                 :: "r"(smem_addr), "l"(gptr) : "memory");
}

#define CP_ASYNC_COMMIT() asm volatile("cp.async.commit_group;\n" ::: "memory")
#define CP_ASYNC_WAIT(n)  asm volatile("cp.async.wait_group %0;\n" :: "n"(n) : "memory")

__device__ __forceinline__ void ldmatrix_x4(uint32_t& r0, uint32_t& r1,
                                            uint32_t& r2, uint32_t& r3,
                                            uint32_t addr) {
    asm volatile("ldmatrix.sync.aligned.m8n8.x4.shared.b16 {%0,%1,%2,%3}, [%4];"
                 : "=r"(r0), "=r"(r1), "=r"(r2), "=r"(r3) : "r"(addr));
}

__device__ __forceinline__ void hmma16816(float& c0, float& c1, float& c2, float& c3,
                                          uint32_t a0, uint32_t a1, uint32_t a2, uint32_t a3,
                                          uint32_t b0, uint32_t b1) {
    asm volatile(
        "mma.sync.aligned.m16n8k16.row.col.f32.f16.f16.f32 "
        "{%0,%1,%2,%3}, {%4,%5,%6,%7}, {%8,%9}, {%0,%1,%2,%3};"
        : "+f"(c0), "+f"(c1), "+f"(c2), "+f"(c3)
        : "r"(a0), "r"(a1), "r"(a2), "r"(a3), "r"(b0), "r"(b1));
}

// ======================= quantization kernels =======================

__global__ void __launch_bounds__(256) quant_w_kernel(const float* __restrict__ w, int K) {
    const int n = blockIdx.x;
    const float4* row = reinterpret_cast<const float4*>(w + (size_t)n * K);
    const int nv = K >> 2;
    const bool fast = (nv == 4 * 256);

    float4 v[4];
    float amax = 0.0f;
    if (fast) {
        #pragma unroll
        for (int j = 0; j < 4; j++) v[j] = row[threadIdx.x + j * 256];
        #pragma unroll
        for (int j = 0; j < 4; j++)
            amax = fmaxf(amax, fmaxf(fmaxf(fabsf(v[j].x), fabsf(v[j].y)),
                                     fmaxf(fabsf(v[j].z), fabsf(v[j].w))));
    } else {
        for (int i = threadIdx.x; i < nv; i += blockDim.x) {
            float4 t = row[i];
            amax = fmaxf(amax, fmaxf(fmaxf(fabsf(t.x), fabsf(t.y)),
                                     fmaxf(fabsf(t.z), fabsf(t.w))));
        }
    }
    #pragma unroll
    for (int o = 16; o; o >>= 1)
        amax = fmaxf(amax, __shfl_xor_sync(0xFFFFFFFF, amax, o));

    __shared__ float s_amax[8];
    __shared__ float s_inv;
    const int wid = threadIdx.x >> 5;
    if ((threadIdx.x & 31) == 0) s_amax[wid] = amax;
    __syncthreads();
    if (threadIdx.x == 0) {
        float a = s_amax[0];
        #pragma unroll
        for (int i = 1; i < 8; i++) a = fmaxf(a, s_amax[i]);
        float sc = (a > 0.0f) ? __fdiv_rn(a, 127.0f) : 1.0f;
        g_wscale[n] = sc;
        s_inv = __fdiv_rn(1.0f, sc);
    }
    __syncthreads();
    const float inv = s_inv;

    __half2* dst = reinterpret_cast<__half2*>(g_wh + (size_t)n * K);
    if (fast) {
        #pragma unroll
        for (int j = 0; j < 4; j++) {
            const int i = threadIdx.x + j * 256;
            float q0 = fminf(fmaxf(rintf(v[j].x * inv), -127.0f), 127.0f);
            float q1 = fminf(fmaxf(rintf(v[j].y * inv), -127.0f), 127.0f);
            float q2 = fminf(fmaxf(rintf(v[j].z * inv), -127.0f), 127.0f);
            float q3 = fminf(fmaxf(rintf(v[j].w * inv), -127.0f), 127.0f);
            dst[2 * i]     = __floats2half2_rn(q0, q1);
            dst[2 * i + 1] = __floats2half2_rn(q2, q3);
        }
    } else {
        for (int i = threadIdx.x; i < nv; i += blockDim.x) {
            float4 t = row[i];
            float q0 = fminf(fmaxf(rintf(t.x * inv), -127.0f), 127.0f);
            float q1 = fminf(fmaxf(rintf(t.y * inv), -127.0f), 127.0f);
            float q2 = fminf(fmaxf(rintf(t.z * inv), -127.0f), 127.0f);
            float q3 = fminf(fmaxf(rintf(t.w * inv), -127.0f), 127.0f);
            dst[2 * i]     = __floats2half2_rn(q0, q1);
            dst[2 * i + 1] = __floats2half2_rn(q2, q3);
        }
    }
}

__global__ void __launch_bounds__(256) quant_x_kernel(const float* __restrict__ x, int K) {
    const int m = blockIdx.x;
    const float4* row = reinterpret_cast<const float4*>(x + (size_t)m * K);
    const int nv = K >> 2;
    const bool fast = (nv == 4 * 256);

    float4 v[4];
    float vmin = 3.0e38f, vmax = -3.0e38f;
    if (fast) {
        #pragma unroll
        for (int j = 0; j < 4; j++) v[j] = row[threadIdx.x + j * 256];
        #pragma unroll
        for (int j = 0; j < 4; j++) {
            vmin = fminf(vmin, fminf(fminf(v[j].x, v[j].y), fminf(v[j].z, v[j].w)));
            vmax = fmaxf(vmax, fmaxf(fmaxf(v[j].x, v[j].y), fmaxf(v[j].z, v[j].w)));
        }
    } else {
        for (int i = threadIdx.x; i < nv; i += blockDim.x) {
            float4 t = row[i];
            vmin = fminf(vmin, fminf(fminf(t.x, t.y), fminf(t.z, t.w)));
            vmax = fmaxf(vmax, fmaxf(fmaxf(t.x, t.y), fmaxf(t.z, t.w)));
        }
    }
    #pragma unroll
    for (int o = 16; o; o >>= 1) {
        vmin = fminf(vmin, __shfl_xor_sync(0xFFFFFFFF, vmin, o));
        vmax = fmaxf(vmax, __shfl_xor_sync(0xFFFFFFFF, vmax, o));
    }
    __shared__ float s_min[8], s_max[8];
    __shared__ float s_inv, s_zp;
    const int wid = threadIdx.x >> 5;
    if ((threadIdx.x & 31) == 0) { s_min[wid] = vmin; s_max[wid] = vmax; }
    __syncthreads();
    if (threadIdx.x == 0) {
        float mn = s_min[0], mx = s_max[0];
        #pragma unroll
        for (int i = 1; i < 8; i++) { mn = fminf(mn, s_min[i]); mx = fmaxf(mx, s_max[i]); }
        float rng = mx - mn;
        float sc = (rng > 0.0f) ? __fdiv_rn(rng, 255.0f) : 1.0f;
        float zp = rintf(__fdiv_rn(-mn, sc));
        g_ascale[m] = sc;
        s_inv = __fdiv_rn(1.0f, sc);
        s_zp = zp;
    }
    __syncthreads();
    const float inv = s_inv, zp = s_zp;

    __half2* dst = reinterpret_cast<__half2*>(g_xh + (size_t)m * K);
    if (fast) {
        #pragma unroll
        for (int j = 0; j < 4; j++) {
            const int i = threadIdx.x + j * 256;
            float q0 = fminf(fmaxf(rintf(v[j].x * inv) + zp, 0.0f), 255.0f) - zp;
            float q1 = fminf(fmaxf(rintf(v[j].y * inv) + zp, 0.0f), 255.0f) - zp;
            float q2 = fminf(fmaxf(rintf(v[j].z * inv) + zp, 0.0f), 255.0f) - zp;
            float q3 = fminf(fmaxf(rintf(v[j].w * inv) + zp, 0.0f), 255.0f) - zp;
            dst[2 * i]     = __floats2half2_rn(q0, q1);
            dst[2 * i + 1] = __floats2half2_rn(q2, q3);
        }
    } else {
        for (int i = threadIdx.x; i < nv; i += blockDim.x) {
            float4 t = row[i];
            float q0 = fminf(fmaxf(rintf(t.x * inv) + zp, 0.0f), 255.0f) - zp;
            float q1 = fminf(fmaxf(rintf(t.y * inv) + zp, 0.0f), 255.0f) - zp;
            float q2 = fminf(fmaxf(rintf(t.z * inv) + zp, 0.0f), 255.0f) - zp;
            float q3 = fminf(fmaxf(rintf(t.w * inv) + zp, 0.0f), 255.0f) - zp;
            dst[2 * i]     = __floats2half2_rn(q0, q1);
            dst[2 * i + 1] = __floats2half2_rn(q2, q3);
        }
    }
}

// ======================= fp16 GEMM kernel v4 =======================

static constexpr int STAGES = 3;
static constexpr int STAGE_BYTES = 32768;                 // A 16K + B 16K
static constexpr int GEMM_SMEM = STAGES * STAGE_BYTES;    // 96KB

__global__ void __launch_bounds__(128)
gemm_kernel(float* __restrict__ out, const float* __restrict__ bias,
            int M, int N, int K) {
    extern __shared__ __align__(1024) uint8_t smem[];
    const uint32_t smem_u32 = smem_to_u32(smem);

    const int tid  = threadIdx.x;
    const int lane = tid & 31;
    const int wid  = tid >> 5;
    const int m0 = blockIdx.y * 128;
    const int n0 = blockIdx.x * 128;
    const int warp_m = (wid >> 1) * 64;
    const int warp_n = (wid & 1) * 64;

    const size_t Kb = (size_t)K * 2;
    const int KT = K >> 6;                // 64-half (128B) chunks

    const uint8_t* gA = reinterpret_cast<const uint8_t*>(g_xh) + (size_t)m0 * Kb;
    const uint8_t* gB = reinterpret_cast<const uint8_t*>(g_wh) + (size_t)n0 * Kb;

    // issue 2 of the 8 copy iterations (4 cp.async); commit at part 3
    auto issue_part = [&](int kt, int s, int part) {
        if (kt < KT) {
            uint32_t sa = smem_u32 + s * STAGE_BYTES;
            uint32_t sb = sa + 16384;
            const uint8_t* ga = gA + (size_t)kt * 128;
            const uint8_t* gb = gB + (size_t)kt * 128;
            #pragma unroll
            for (int jj = 0; jj < 2; jj++) {
                int j = part * 2 + jj;
                int idx = tid + j * 128;
                int row = idx >> 3;
                int c   = idx & 7;
                int cs  = c ^ (row & 7);
                cp_async16(sa + row * 128 + (cs << 4), ga + (size_t)row * Kb + c * 16);
                cp_async16(sb + row * 128 + (cs << 4), gb + (size_t)row * Kb + c * 16);
            }
        }
        if (part == 3) CP_ASYNC_COMMIT();
    };

    auto issue_full = [&](int kt, int s) {
        #pragma unroll
        for (int p = 0; p < 4; p++) issue_part(kt, s, p);
    };

    const int a_row = lane & 15;
    const int a_cs  = lane >> 4;
    const int a_swz = a_row & 7;
    const int b_row = (lane & 7) + ((lane >> 4) << 3);
    const int b_cs  = (lane >> 3) & 1;
    const int b_swz = b_row & 7;

    float acc[4][8][4];
    #pragma unroll
    for (int i = 0; i < 4; i++)
        #pragma unroll
        for (int j = 0; j < 8; j++)
            #pragma unroll
            for (int r = 0; r < 4; r++) acc[i][j][r] = 0.0f;

    uint32_t af[2][4][4];
    uint32_t bf[2][4][4];

    auto load_frags = [&](uint32_t sa, uint32_t sb, int ks, int buf) {
        #pragma unroll
        for (int mf = 0; mf < 4; mf++) {
            uint32_t addr = sa + (warp_m + mf * 16 + a_row) * 128
                          + (((2 * ks + a_cs) ^ a_swz) << 4);
            ldmatrix_x4(af[buf][mf][0], af[buf][mf][1],
                        af[buf][mf][2], af[buf][mf][3], addr);
        }
        #pragma unroll
        for (int p = 0; p < 4; p++) {
            uint32_t addr = sb + (warp_n + p * 16 + b_row) * 128
                          + (((2 * ks + b_cs) ^ b_swz) << 4);
            ldmatrix_x4(bf[buf][p][0], bf[buf][p][1],
                        bf[buf][p][2], bf[buf][p][3], addr);
        }
    };

    auto compute = [&](int buf) {
        #pragma unroll
        for (int mf = 0; mf < 4; mf++) {
            #pragma unroll
            for (int nf = 0; nf < 8; nf++) {
                const int p = nf >> 1, h = (nf & 1) << 1;
                hmma16816(acc[mf][nf][0], acc[mf][nf][1],
                          acc[mf][nf][2], acc[mf][nf][3],
                          af[buf][mf][0], af[buf][mf][1],
                          af[buf][mf][2], af[buf][mf][3],
                          bf[buf][p][h], bf[buf][p][h + 1]);
            }
        }
    };

    #pragma unroll
    for (int s = 0; s < STAGES - 1; s++) issue_full(s, s);

    for (int kt = 0; kt < KT; kt++) {
        CP_ASYNC_WAIT(STAGES - 2);
        __syncthreads();

        const int s = kt % STAGES;
        const uint32_t sa = smem_u32 + s * STAGE_BYTES;
        const uint32_t sb = sa + 16384;
        const int kt_next = kt + STAGES - 1;
        const int s_next = kt_next % STAGES;

        load_frags(sa, sb, 0, 0);

        #pragma unroll
        for (int ks = 0; ks < 4; ks++) {
            issue_part(kt_next, s_next, ks);     // 4 cp.async per step
            if (ks < 3) load_frags(sa, sb, ks + 1, (ks + 1) & 1);
            compute(ks & 1);
        }
    }

    // ================= epilogue =================
    #pragma unroll
    for (int mf = 0; mf < 4; mf++) {
        const int gr0 = m0 + warp_m + mf * 16 + (lane >> 2);
        const int gr1 = gr0 + 8;
        const float sa0 = g_ascale[gr0];
        const float sa1 = g_ascale[gr1];
        #pragma unroll
        for (int nf = 0; nf < 8; nf++) {
            const int gc = n0 + warp_n + nf * 8 + 2 * (lane & 3);
            const float sw0 = g_wscale[gc], sw1 = g_wscale[gc + 1];
            const float bb0 = bias[gc],     bb1 = bias[gc + 1];
            float2 v0, v1;
            v0.x = acc[mf][nf][0] * (sa0 * sw0) + bb0;
            v0.y = acc[mf][nf][1] * (sa0 * sw1) + bb1;
            v1.x = acc[mf][nf][2] * (sa1 * sw0) + bb0;
            v1.y = acc[mf][nf][3] * (sa1 * sw1) + bb1;
            *reinterpret_cast<float2*>(out + (size_t)gr0 * N + gc) = v0;
            *reinterpret_cast<float2*>(out + (size_t)gr1 * N + gc) = v1;
        }
    }
}

// ======================= launch =======================

extern "C" void kernel_launch(void* const* d_in, const int* in_sizes, int n_in,
                              void* d_out, int out_size) {
    const float* x    = (const float*)d_in[0];
    const float* w    = (const float*)d_in[1];
    const float* bias = (const float*)d_in[2];
    float* out        = (float*)d_out;

    const int N = in_sizes[2];          // 4096
    const int K = in_sizes[1] / N;      // 4096
    const int M = in_sizes[0] / K;      // 8192

    cudaFuncSetAttribute(gemm_kernel,
                         cudaFuncAttributeMaxDynamicSharedMemorySize, GEMM_SMEM);

    quant_w_kernel<<<N, 256>>>(w, K);
    quant_x_kernel<<<M, 256>>>(x, K);

    dim3 grid(N / 128, M / 128);
    gemm_kernel<<<grid, 128, GEMM_SMEM>>>(out, bias, M, N, K);
}

// round 11
// speedup vs baseline: 4.4079x; 1.0288x over previous
#include <cuda_runtime.h>
#include <cuda_fp16.h>
#include <cstdint>

// =====================================================================
// QuantLinear W8A8 — fp16 legacy-HMMA GEMM (mma.sync m16n8k16), v5.
//   A = (Xq - zp[m]) exact in fp16; B = Wq exact in fp16
//   acc = A @ B^T (fp32), Y = acc * sa[m]*sw[n] + bias[n]
// v5: cross-barrier fragment prefetch (barrier moved to chunk tail,
// next chunk's ks=0 frags loaded before it) + merged quant kernel.
// GEMM: CTA 128x128, 4 warps (64x64), BK=64, XOR-8 swizzle, 3 stages.
// =====================================================================

static constexpr int M_MAX = 8192;
static constexpr int N_MAX = 4096;
static constexpr int K_MAX = 4096;

__device__ __half g_xh[(size_t)M_MAX * K_MAX];   // Xq - zp
__device__ __half g_wh[(size_t)N_MAX * K_MAX];   // Wq
__device__ float  g_ascale[M_MAX];
__device__ float  g_wscale[N_MAX];

// ======================= PTX helpers =======================

__device__ __forceinline__ uint32_t smem_to_u32(const void* p) {
    uint32_t a;
    asm("{ .reg .u64 t; cvta.to.shared.u64 t, %1; cvt.u32.u64 %0, t; }"
        : "=r"(a) : "l"(p));
    return a;
}

__device__ __forceinline__ void cp_async16(uint32_t smem_addr, const void* gptr) {
    asm volatile("cp.async.cg.shared.global [%0], [%1], 16;\n"
                 :: "r"(smem_addr), "l"(gptr) : "memory");
}

#define CP_ASYNC_COMMIT() asm volatile("cp.async.commit_group;\n" ::: "memory")
#define CP_ASYNC_WAIT(n)  asm volatile("cp.async.wait_group %0;\n" :: "n"(n) : "memory")

__device__ __forceinline__ void ldmatrix_x4(uint32_t& r0, uint32_t& r1,
                                            uint32_t& r2, uint32_t& r3,
                                            uint32_t addr) {
    asm volatile("ldmatrix.sync.aligned.m8n8.x4.shared.b16 {%0,%1,%2,%3}, [%4];"
                 : "=r"(r0), "=r"(r1), "=r"(r2), "=r"(r3) : "r"(addr));
}

__device__ __forceinline__ void hmma16816(float& c0, float& c1, float& c2, float& c3,
                                          uint32_t a0, uint32_t a1, uint32_t a2, uint32_t a3,
                                          uint32_t b0, uint32_t b1) {
    asm volatile(
        "mma.sync.aligned.m16n8k16.row.col.f32.f16.f16.f32 "
        "{%0,%1,%2,%3}, {%4,%5,%6,%7}, {%8,%9}, {%0,%1,%2,%3};"
        : "+f"(c0), "+f"(c1), "+f"(c2), "+f"(c3)
        : "r"(a0), "r"(a1), "r"(a2), "r"(a3), "r"(b0), "r"(b1));
}

// ======================= merged quantization kernel =======================
// blockIdx.x <  Nrows : weight row  (symmetric s8 -> fp16)
// blockIdx.x >= Nrows : activation row (asymmetric u8, store Xq-zp in fp16)

__global__ void __launch_bounds__(256)
quant_kernel(const float* __restrict__ w, const float* __restrict__ x,
             int Nrows, int K) {
    const bool is_w = (blockIdx.x < Nrows);
    const int r = is_w ? blockIdx.x : (blockIdx.x - Nrows);
    const float4* row = reinterpret_cast<const float4*>(
        (is_w ? w : x) + (size_t)r * K);
    const int nv = K >> 2;
    const bool fast = (nv == 4 * 256);

    float4 v[4];
    float vmin = 3.0e38f, vmax = -3.0e38f;
    if (fast) {
        #pragma unroll
        for (int j = 0; j < 4; j++) v[j] = row[threadIdx.x + j * 256];
        #pragma unroll
        for (int j = 0; j < 4; j++) {
            vmin = fminf(vmin, fminf(fminf(v[j].x, v[j].y), fminf(v[j].z, v[j].w)));
            vmax = fmaxf(vmax, fmaxf(fmaxf(v[j].x, v[j].y), fmaxf(v[j].z, v[j].w)));
        }
    } else {
        for (int i = threadIdx.x; i < nv; i += blockDim.x) {
            float4 t = row[i];
            vmin = fminf(vmin, fminf(fminf(t.x, t.y), fminf(t.z, t.w)));
            vmax = fmaxf(vmax, fmaxf(fmaxf(t.x, t.y), fmaxf(t.z, t.w)));
        }
    }
    #pragma unroll
    for (int o = 16; o; o >>= 1) {
        vmin = fminf(vmin, __shfl_xor_sync(0xFFFFFFFF, vmin, o));
        vmax = fmaxf(vmax, __shfl_xor_sync(0xFFFFFFFF, vmax, o));
    }
    __shared__ float s_min[8], s_max[8];
    __shared__ float s_inv, s_zp;
    const int wid = threadIdx.x >> 5;
    if ((threadIdx.x & 31) == 0) { s_min[wid] = vmin; s_max[wid] = vmax; }
    __syncthreads();
    if (threadIdx.x == 0) {
        float mn = s_min[0], mx = s_max[0];
        #pragma unroll
        for (int i = 1; i < 8; i++) { mn = fminf(mn, s_min[i]); mx = fmaxf(mx, s_max[i]); }
        if (is_w) {
            float a = fmaxf(fabsf(mn), fabsf(mx));
            float sc = (a > 0.0f) ? __fdiv_rn(a, 127.0f) : 1.0f;
            g_wscale[r] = sc;
            s_inv = __fdiv_rn(1.0f, sc);
            s_zp = 0.0f;
        } else {
            float rng = mx - mn;
            float sc = (rng > 0.0f) ? __fdiv_rn(rng, 255.0f) : 1.0f;
            float zp = rintf(__fdiv_rn(-mn, sc));
            g_ascale[r] = sc;
            s_inv = __fdiv_rn(1.0f, sc);
            s_zp = zp;
        }
    }
    __syncthreads();
    const float inv = s_inv, zp = s_zp;

    __half2* dst = reinterpret_cast<__half2*>(
        (is_w ? g_wh : g_xh) + (size_t)r * K);

    if (is_w) {
        if (fast) {
            #pragma unroll
            for (int j = 0; j < 4; j++) {
                const int i = threadIdx.x + j * 256;
                float q0 = fminf(fmaxf(rintf(v[j].x * inv), -127.0f), 127.0f);
                float q1 = fminf(fmaxf(rintf(v[j].y * inv), -127.0f), 127.0f);
                float q2 = fminf(fmaxf(rintf(v[j].z * inv), -127.0f), 127.0f);
                float q3 = fminf(fmaxf(rintf(v[j].w * inv), -127.0f), 127.0f);
                dst[2 * i]     = __floats2half2_rn(q0, q1);
                dst[2 * i + 1] = __floats2half2_rn(q2, q3);
            }
        } else {
            for (int i = threadIdx.x; i < nv; i += blockDim.x) {
                float4 t = row[i];
                float q0 = fminf(fmaxf(rintf(t.x * inv), -127.0f), 127.0f);
                float q1 = fminf(fmaxf(rintf(t.y * inv), -127.0f), 127.0f);
                float q2 = fminf(fmaxf(rintf(t.z * inv), -127.0f), 127.0f);
                float q3 = fminf(fmaxf(rintf(t.w * inv), -127.0f), 127.0f);
                dst[2 * i]     = __floats2half2_rn(q0, q1);
                dst[2 * i + 1] = __floats2half2_rn(q2, q3);
            }
        }
    } else {
        if (fast) {
            #pragma unroll
            for (int j = 0; j < 4; j++) {
                const int i = threadIdx.x + j * 256;
                float q0 = fminf(fmaxf(rintf(v[j].x * inv) + zp, 0.0f), 255.0f) - zp;
                float q1 = fminf(fmaxf(rintf(v[j].y * inv) + zp, 0.0f), 255.0f) - zp;
                float q2 = fminf(fmaxf(rintf(v[j].z * inv) + zp, 0.0f), 255.0f) - zp;
                float q3 = fminf(fmaxf(rintf(v[j].w * inv) + zp, 0.0f), 255.0f) - zp;
                dst[2 * i]     = __floats2half2_rn(q0, q1);
                dst[2 * i + 1] = __floats2half2_rn(q2, q3);
            }
        } else {
            for (int i = threadIdx.x; i < nv; i += blockDim.x) {
                float4 t = row[i];
                float q0 = fminf(fmaxf(rintf(t.x * inv) + zp, 0.0f), 255.0f) - zp;
                float q1 = fminf(fmaxf(rintf(t.y * inv) + zp, 0.0f), 255.0f) - zp;
                float q2 = fminf(fmaxf(rintf(t.z * inv) + zp, 0.0f), 255.0f) - zp;
                float q3 = fminf(fmaxf(rintf(t.w * inv) + zp, 0.0f), 255.0f) - zp;
                dst[2 * i]     = __floats2half2_rn(q0, q1);
                dst[2 * i + 1] = __floats2half2_rn(q2, q3);
            }
        }
    }
}

// ======================= fp16 GEMM kernel v5 =======================

static constexpr int STAGES = 3;
static constexpr int STAGE_BYTES = 32768;                 // A 16K + B 16K
static constexpr int GEMM_SMEM = STAGES * STAGE_BYTES;    // 96KB

__global__ void __launch_bounds__(128)
gemm_kernel(float* __restrict__ out, const float* __restrict__ bias,
            int M, int N, int K) {
    extern __shared__ __align__(1024) uint8_t smem[];
    const uint32_t smem_u32 = smem_to_u32(smem);

    const int tid  = threadIdx.x;
    const int lane = tid & 31;
    const int wid  = tid >> 5;
    const int m0 = blockIdx.y * 128;
    const int n0 = blockIdx.x * 128;
    const int warp_m = (wid >> 1) * 64;
    const int warp_n = (wid & 1) * 64;

    const size_t Kb = (size_t)K * 2;
    const int KT = K >> 6;                // 64-half (128B) chunks

    const uint8_t* gA = reinterpret_cast<const uint8_t*>(g_xh) + (size_t)m0 * Kb;
    const uint8_t* gB = reinterpret_cast<const uint8_t*>(g_wh) + (size_t)n0 * Kb;

    auto issue_part = [&](int kt, int s, int part) {
        if (kt < KT) {
            uint32_t sa = smem_u32 + s * STAGE_BYTES;
            uint32_t sb = sa + 16384;
            const uint8_t* ga = gA + (size_t)kt * 128;
            const uint8_t* gb = gB + (size_t)kt * 128;
            #pragma unroll
            for (int jj = 0; jj < 2; jj++) {
                int j = part * 2 + jj;
                int idx = tid + j * 128;
                int row = idx >> 3;
                int c   = idx & 7;
                int cs  = c ^ (row & 7);
                cp_async16(sa + row * 128 + (cs << 4), ga + (size_t)row * Kb + c * 16);
                cp_async16(sb + row * 128 + (cs << 4), gb + (size_t)row * Kb + c * 16);
            }
        }
        if (part == 3) CP_ASYNC_COMMIT();
    };

    auto issue_full = [&](int kt, int s) {
        #pragma unroll
        for (int p = 0; p < 4; p++) issue_part(kt, s, p);
    };

    const int a_row = lane & 15;
    const int a_cs  = lane >> 4;
    const int a_swz = a_row & 7;
    const int b_row = (lane & 7) + ((lane >> 4) << 3);
    const int b_cs  = (lane >> 3) & 1;
    const int b_swz = b_row & 7;

    float acc[4][8][4];
    #pragma unroll
    for (int i = 0; i < 4; i++)
        #pragma unroll
        for (int j = 0; j < 8; j++)
            #pragma unroll
            for (int r = 0; r < 4; r++) acc[i][j][r] = 0.0f;

    uint32_t af[2][4][4];
    uint32_t bf[2][4][4];

    auto load_frags = [&](uint32_t sa, uint32_t sb, int ks, int buf) {
        #pragma unroll
        for (int mf = 0; mf < 4; mf++) {
            uint32_t addr = sa + (warp_m + mf * 16 + a_row) * 128
                          + (((2 * ks + a_cs) ^ a_swz) << 4);
            ldmatrix_x4(af[buf][mf][0], af[buf][mf][1],
                        af[buf][mf][2], af[buf][mf][3], addr);
        }
        #pragma unroll
        for (int p = 0; p < 4; p++) {
            uint32_t addr = sb + (warp_n + p * 16 + b_row) * 128
                          + (((2 * ks + b_cs) ^ b_swz) << 4);
            ldmatrix_x4(bf[buf][p][0], bf[buf][p][1],
                        bf[buf][p][2], bf[buf][p][3], addr);
        }
    };

    auto compute = [&](int buf) {
        #pragma unroll
        for (int mf = 0; mf < 4; mf++) {
            #pragma unroll
            for (int nf = 0; nf < 8; nf++) {
                const int p = nf >> 1, h = (nf & 1) << 1;
                hmma16816(acc[mf][nf][0], acc[mf][nf][1],
                          acc[mf][nf][2], acc[mf][nf][3],
                          af[buf][mf][0], af[buf][mf][1],
                          af[buf][mf][2], af[buf][mf][3],
                          bf[buf][p][h], bf[buf][p][h + 1]);
            }
        }
    };

    // prologue: stages 0,1 in flight; stage 0 ready; prefetch ks=0 frags
    issue_full(0, 0);
    issue_full(1, 1);
    CP_ASYNC_WAIT(1);
    __syncthreads();
    load_frags(smem_u32, smem_u32 + 16384, 0, 0);

    for (int kt = 0; kt < KT; kt++) {
        const int s = kt % STAGES;
        const uint32_t sa = smem_u32 + s * STAGE_BYTES;
        const uint32_t sb = sa + 16384;
        const int kt_next = kt + STAGES - 1;
        const int s_next = kt_next % STAGES;
        const int s1 = (kt + 1) % STAGES;
        const uint32_t sa1 = smem_u32 + s1 * STAGE_BYTES;
        const uint32_t sb1 = sa1 + 16384;

        #pragma unroll
        for (int ks = 0; ks < 4; ks++) {
            issue_part(kt_next, s_next, ks);       // commit at ks==3
            if (ks < 3) {
                load_frags(sa, sb, ks + 1, (ks + 1) & 1);
            } else {
                CP_ASYNC_WAIT(1);                  // stage kt+1 data landed
                __syncthreads();                   // all reads of stage kt done
                load_frags(sa1, sb1, 0, 0);        // prefetch next chunk ks=0
            }
            compute(ks & 1);
        }
    }

    // ================= epilogue =================
    #pragma unroll
    for (int mf = 0; mf < 4; mf++) {
        const int gr0 = m0 + warp_m + mf * 16 + (lane >> 2);
        const int gr1 = gr0 + 8;
        const float sa0 = g_ascale[gr0];
        const float sa1 = g_ascale[gr1];
        #pragma unroll
        for (int nf = 0; nf < 8; nf++) {
            const int gc = n0 + warp_n + nf * 8 + 2 * (lane & 3);
            const float sw0 = g_wscale[gc], sw1 = g_wscale[gc + 1];
            const float bb0 = bias[gc],     bb1 = bias[gc + 1];
            float2 v0, v1;
            v0.x = acc[mf][nf][0] * (sa0 * sw0) + bb0;
            v0.y = acc[mf][nf][1] * (sa0 * sw1) + bb1;
            v1.x = acc[mf][nf][2] * (sa1 * sw0) + bb0;
            v1.y = acc[mf][nf][3] * (sa1 * sw1) + bb1;
            *reinterpret_cast<float2*>(out + (size_t)gr0 * N + gc) = v0;
            *reinterpret_cast<float2*>(out + (size_t)gr1 * N + gc) = v1;
        }
    }
}

// ======================= launch =======================

extern "C" void kernel_launch(void* const* d_in, const int* in_sizes, int n_in,
                              void* d_out, int out_size) {
    const float* x    = (const float*)d_in[0];
    const float* w    = (const float*)d_in[1];
    const float* bias = (const float*)d_in[2];
    float* out        = (float*)d_out;

    const int N = in_sizes[2];          // 4096
    const int K = in_sizes[1] / N;      // 4096
    const int M = in_sizes[0] / K;      // 8192

    cudaFuncSetAttribute(gemm_kernel,
                         cudaFuncAttributeMaxDynamicSharedMemorySize, GEMM_SMEM);

    quant_kernel<<<N + M, 256>>>(w, x, N, K);

    dim3 grid(N / 128, M / 128);
    gemm_kernel<<<grid, 128, GEMM_SMEM>>>(out, bias, M, N, K);
}